// round 1
// baseline (speedup 1.0000x reference)
#include <cuda_runtime.h>

#define C 64
#define KOFF 27
#define ROWS 256
#define THREADS 256
#define FSS 65                 // padded feature-tile row stride (floats)
#define EPSV 1e-4f
#define SMEM_FLOATS (C*C + ROWS*FSS)
#define SMEM_BYTES (SMEM_FLOATS * 4)

__device__ float g_sum[C];
__device__ float g_sq[C];
__device__ float g_scale[C];
__device__ float g_shift[C];

__global__ void zero_stats_kernel() {
    int t = threadIdx.x;
    if (t < C) { g_sum[t] = 0.0f; g_sq[t] = 0.0f; }
}

__global__ __launch_bounds__(THREADS, 2)
void conv_kernel(const float* __restrict__ feat,
                 const float* __restrict__ Wg,
                 const float* __restrict__ bias,
                 const int*   __restrict__ nbr,
                 float* __restrict__ out, int n)
{
    extern __shared__ float smem[];
    float* Wk = smem;            // [64][64]
    float* fs = smem + C * C;    // [ROWS][FSS]

    const int tid  = threadIdx.x;
    const int tc   = tid & 7;         // col group: cols tc*8 .. tc*8+7
    const int trow = tid >> 3;        // row group: rows trow*8 .. trow*8+7
    const int row0 = blockIdx.x * ROWS;
    const int trow8 = trow * 8;

    const float4* feat4 = (const float4*)feat;
    const float4* Wg4   = (const float4*)Wg;

    float acc[8][8];
#pragma unroll
    for (int r = 0; r < 8; r++)
#pragma unroll
        for (int j = 0; j < 8; j++) acc[r][j] = 0.0f;

    for (int k = 0; k < KOFF; k++) {
        __syncthreads();   // protect smem reuse from previous iteration's compute

        // stage W_k: 4096 floats = 1024 float4
        for (int e = tid; e < (C * C) / 4; e += THREADS) {
            ((float4*)Wk)[e] = Wg4[k * (C * C / 4) + e];
        }

        // gather 256 feature rows (64 floats each) for offset k
        for (int e = tid; e < ROWS * 16; e += THREADS) {
            const int r   = e >> 4;
            const int seg = e & 15;
            const int grow = row0 + r;
            int idx = n;
            if (grow < n) idx = nbr[grow * KOFF + k];
            float4 v = make_float4(0.f, 0.f, 0.f, 0.f);
            if (idx < n) v = feat4[idx * 16 + seg];
            float* d = &fs[r * FSS + seg * 4];
            d[0] = v.x; d[1] = v.y; d[2] = v.z; d[3] = v.w;
        }
        __syncthreads();

        // mainloop: acc[r][j] += fs[row][i] * Wk[i][col]
#pragma unroll 4
        for (int i = 0; i < C; i++) {
            const float4 w0 = *(const float4*)(Wk + i * C + tc * 8);
            const float4 w1 = *(const float4*)(Wk + i * C + tc * 8 + 4);
            float f[8];
#pragma unroll
            for (int r = 0; r < 8; r++) f[r] = fs[(trow8 + r) * FSS + i];
#pragma unroll
            for (int r = 0; r < 8; r++) {
                acc[r][0] += f[r] * w0.x;
                acc[r][1] += f[r] * w0.y;
                acc[r][2] += f[r] * w0.z;
                acc[r][3] += f[r] * w0.w;
                acc[r][4] += f[r] * w1.x;
                acc[r][5] += f[r] * w1.y;
                acc[r][6] += f[r] * w1.z;
                acc[r][7] += f[r] * w1.w;
            }
        }
    }

    // epilogue: add bias, store raw conv output, accumulate channel sums/sumsq
    const float4 b0 = *(const float4*)(bias + tc * 8);
    const float4 b1 = *(const float4*)(bias + tc * 8 + 4);

    float s[8], q[8];
#pragma unroll
    for (int j = 0; j < 8; j++) { s[j] = 0.0f; q[j] = 0.0f; }

#pragma unroll
    for (int r = 0; r < 8; r++) {
        const int grow = row0 + trow8 + r;
        if (grow < n) {
            float v[8];
            v[0] = acc[r][0] + b0.x; v[1] = acc[r][1] + b0.y;
            v[2] = acc[r][2] + b0.z; v[3] = acc[r][3] + b0.w;
            v[4] = acc[r][4] + b1.x; v[5] = acc[r][5] + b1.y;
            v[6] = acc[r][6] + b1.z; v[7] = acc[r][7] + b1.w;
            float4 o0 = make_float4(v[0], v[1], v[2], v[3]);
            float4 o1 = make_float4(v[4], v[5], v[6], v[7]);
            *(float4*)(out + (size_t)grow * C + tc * 8)     = o0;
            *(float4*)(out + (size_t)grow * C + tc * 8 + 4) = o1;
#pragma unroll
            for (int j = 0; j < 8; j++) { s[j] += v[j]; q[j] += v[j] * v[j]; }
        }
    }

    // warp-level reduce across trow groups (lanes tc, tc+8, tc+16, tc+24)
#pragma unroll
    for (int j = 0; j < 8; j++) {
        s[j] += __shfl_xor_sync(0xFFFFFFFFu, s[j], 8);
        s[j] += __shfl_xor_sync(0xFFFFFFFFu, s[j], 16);
        q[j] += __shfl_xor_sync(0xFFFFFFFFu, q[j], 8);
        q[j] += __shfl_xor_sync(0xFFFFFFFFu, q[j], 16);
    }

    __syncthreads();  // done with fs/Wk; reuse smem for reduction
    float* ssum = smem;
    float* ssq  = smem + C;
    if (tid < 2 * C) smem[tid] = 0.0f;
    __syncthreads();

    if ((tid & 31) < 8) {   // one lane per (warp, tc)
#pragma unroll
        for (int j = 0; j < 8; j++) {
            atomicAdd(&ssum[tc * 8 + j], s[j]);
            atomicAdd(&ssq[tc * 8 + j],  q[j]);
        }
    }
    __syncthreads();
    if (tid < C)           atomicAdd(&g_sum[tid], ssum[tid]);
    else if (tid < 2 * C)  atomicAdd(&g_sq[tid - C], ssq[tid - C]);
}

__global__ void stats_kernel(const float* __restrict__ gamma,
                             const float* __restrict__ beta, float inv_n)
{
    int c = threadIdx.x;
    if (c < C) {
        float m   = g_sum[c] * inv_n;
        float var = g_sq[c] * inv_n - m * m;
        float rs  = rsqrtf(var + EPSV);
        float sc  = gamma[c] * rs;
        g_scale[c] = sc;
        g_shift[c] = beta[c] - sc * m;
    }
}

__global__ void apply_kernel(float* __restrict__ out, int total4)
{
    const float4* sc4 = (const float4*)g_scale;
    const float4* sh4 = (const float4*)g_shift;
    for (int i = blockIdx.x * blockDim.x + threadIdx.x; i < total4;
         i += gridDim.x * blockDim.x) {
        float4 v  = ((float4*)out)[i];
        float4 sc = sc4[i & 15];
        float4 sh = sh4[i & 15];
        float y0 = v.x * sc.x + sh.x;
        float y1 = v.y * sc.y + sh.y;
        float y2 = v.z * sc.z + sh.z;
        float y3 = v.w * sc.w + sh.w;
        const float L = 1.0f / 3.0f;
        v.x = y0 > 0.f ? y0 : y0 * L;
        v.y = y1 > 0.f ? y1 : y1 * L;
        v.z = y2 > 0.f ? y2 : y2 * L;
        v.w = y3 > 0.f ? y3 : y3 * L;
        ((float4*)out)[i] = v;
    }
}

extern "C" void kernel_launch(void* const* d_in, const int* in_sizes, int n_in,
                              void* d_out, int out_size)
{
    const float* feat  = (const float*)d_in[0];
    const float* W     = (const float*)d_in[1];
    const float* bias  = (const float*)d_in[2];
    const float* gamma = (const float*)d_in[3];
    const float* beta  = (const float*)d_in[4];
    const int*   nbr   = (const int*)d_in[5];
    const int n = in_sizes[0] / C;

    cudaFuncSetAttribute(conv_kernel,
                         cudaFuncAttributeMaxDynamicSharedMemorySize, SMEM_BYTES);

    zero_stats_kernel<<<1, 128>>>();
    conv_kernel<<<(n + ROWS - 1) / ROWS, THREADS, SMEM_BYTES>>>(
        feat, W, bias, nbr, (float*)d_out, n);
    stats_kernel<<<1, C>>>(gamma, beta, 1.0f / (float)n);
    apply_kernel<<<2048, 256>>>((float*)d_out, n * (C / 4));
}

// round 3
// speedup vs baseline: 2.0038x; 2.0038x over previous
#include <cuda_runtime.h>
#include <cuda_bf16.h>
#include <cstdint>

#define CDIM 64
#define KOFF 27
#define MTILE 128
#define THREADS 256
#define EPSV 1e-4f

// smem layout (bytes)
#define SM_RED   0                      // 128 floats
#define SM_BIAS  512                    // 64 floats
#define SM_A(b)  (1024 + (b)*32768)     // A: 128 rows x 256B (bf16 hi|lo, swizzled)
#define SM_B(b)  (66560 + (b)*16384)    // B: 64 rows x 256B
#define SMEM_BYTES 99328

__device__ float g_sum[CDIM];
__device__ float g_sq[CDIM];
__device__ float g_scale[CDIM];
__device__ float g_shift[CDIM];
__device__ __align__(16) __nv_bfloat16 WB[KOFF * 8192];  // B image: [k][n=64][kk=128] swizzled

__device__ __forceinline__ uint32_t smem_u32(const void* p) {
    uint32_t a;
    asm("{ .reg .u64 t; cvta.to.shared.u64 t, %1; cvt.u32.u64 %0, t; }" : "=r"(a) : "l"(p));
    return a;
}
__device__ __forceinline__ void cp16(uint32_t dst, const void* src) {
    asm volatile("cp.async.cg.shared.global [%0], [%1], 16;"
                 :: "r"(dst), "l"(__cvta_generic_to_global(src)));
}
__device__ __forceinline__ void ldsm4(uint32_t* r, uint32_t addr) {
    asm volatile("ldmatrix.sync.aligned.m8n8.x4.shared.b16 {%0,%1,%2,%3}, [%4];"
                 : "=r"(r[0]), "=r"(r[1]), "=r"(r[2]), "=r"(r[3]) : "r"(addr));
}
__device__ __forceinline__ void mma16816(float* d, const uint32_t* a, const uint32_t* b) {
    asm volatile("mma.sync.aligned.m16n8k16.row.col.f32.bf16.bf16.f32 "
                 "{%0,%1,%2,%3}, {%4,%5,%6,%7}, {%8,%9}, {%0,%1,%2,%3};"
                 : "+f"(d[0]), "+f"(d[1]), "+f"(d[2]), "+f"(d[3])
                 : "r"(a[0]), "r"(a[1]), "r"(a[2]), "r"(a[3]), "r"(b[0]), "r"(b[1]));
}
__device__ __forceinline__ void sts4(uint32_t a, uint32_t x, uint32_t y, uint32_t z, uint32_t w) {
    asm volatile("st.shared.v4.u32 [%0], {%1,%2,%3,%4};" :: "r"(a), "r"(x), "r"(y), "r"(z), "r"(w) : "memory");
}
__device__ __forceinline__ uint32_t bfpack(float a, float b) {
    __nv_bfloat162 t = __floats2bfloat162_rn(a, b);
    return *reinterpret_cast<uint32_t*>(&t);
}

__global__ void zero_stats_kernel() {
    int t = threadIdx.x;
    if (t < CDIM) { g_sum[t] = 0.0f; g_sq[t] = 0.0f; }
}

// W[k][cin][cout] -> WB[k]: rows n=cout (256B = 16 chunks of 8 bf16),
// kk = cin for hi (chunks 0-7), 64+cin for lo (chunks 8-15), chunk ^= (n&7).
__global__ void wprep_kernel(const float* __restrict__ W) {
    int k = blockIdx.x;
    for (int e = threadIdx.x; e < 4096; e += 256) {
        int nn = e & 63, kk = e >> 6;
        float w = W[k * 4096 + kk * 64 + nn];
        __nv_bfloat16 hb = __float2bfloat16_rn(w);
        float hf = __bfloat162float(hb);
        __nv_bfloat16 lb = __float2bfloat16_rn(w - hf);
        int ch = (kk >> 3) ^ (nn & 7);
        int cl = ((kk >> 3) + 8) ^ (nn & 7);
        WB[k * 8192 + nn * 128 + ch * 8 + (kk & 7)] = hb;
        WB[k * 8192 + nn * 128 + cl * 8 + (kk & 7)] = lb;
    }
}

__global__ __launch_bounds__(THREADS, 2)
void conv_kernel(const float* __restrict__ feat,
                 const float* __restrict__ bias,
                 const int*   __restrict__ nbr,
                 float* __restrict__ out, int n)
{
    extern __shared__ char smem[];
    const uint32_t sbase = smem_u32(smem);
    float* sred = (float*)(smem + SM_RED);
    float* sb   = (float*)(smem + SM_BIAS);

    const int tid = threadIdx.x;
    const int wid = tid >> 5, lane = tid & 31;
    const int warp_m = wid & 3, warp_n = wid >> 2;
    const int row0 = blockIdx.x * MTILE;
    const float4* feat4 = (const float4*)feat;

    if (tid < 128) sred[tid] = 0.0f;
    if (tid < CDIM) sb[tid] = bias[tid];

    // gather mapping: 2 threads per row
    const int gr = tid >> 1, gh = tid & 1;

    // ldmatrix lane address components
    const int r7 = lane & 7;
    const int arow = ((lane >> 3) & 1) * 8 + r7;        // A quadrant rows
    const int asel = lane >> 4;                          // A chunk select
    const int brow = ((lane >> 4) & 1) * 8 + r7;        // B quadrant rows
    const int bsel = (lane >> 3) & 1;                    // B chunk select

    float acc[2][4][4];
#pragma unroll
    for (int mt = 0; mt < 2; mt++)
#pragma unroll
        for (int nt = 0; nt < 4; nt++)
#pragma unroll
            for (int j = 0; j < 4; j++) acc[mt][nt][j] = 0.0f;

    // ---- helpers as lambdas ----
    auto gatherA = [&](int k, float4 v[8]) {
        const int grow = row0 + gr;
        int idx = (grow < n) ? nbr[grow * KOFF + k] : n;
        const bool ok = idx < n;
        const float4* src = feat4 + (size_t)(ok ? idx : 0) * 16 + gh * 8;
#pragma unroll
        for (int j = 0; j < 8; j++)
            v[j] = ok ? src[j] : make_float4(0.f, 0.f, 0.f, 0.f);
    };
    auto stsA = [&](uint32_t abuf, const float4 v[8]) {
        const uint32_t rowaddr = abuf + gr * 256;
        const int rx = gr & 7;
#pragma unroll
        for (int t = 0; t < 4; t++) {
            float4 p = v[2 * t], q = v[2 * t + 1];
            __nv_bfloat162 h0 = __floats2bfloat162_rn(p.x, p.y);
            __nv_bfloat162 h1 = __floats2bfloat162_rn(p.z, p.w);
            __nv_bfloat162 h2 = __floats2bfloat162_rn(q.x, q.y);
            __nv_bfloat162 h3 = __floats2bfloat162_rn(q.z, q.w);
            uint32_t ha = rowaddr + (((4 * gh + t) ^ rx) << 4);
            sts4(ha, *(uint32_t*)&h0, *(uint32_t*)&h1, *(uint32_t*)&h2, *(uint32_t*)&h3);
            float2 f0 = __bfloat1622float2(h0), f1 = __bfloat1622float2(h1);
            float2 f2 = __bfloat1622float2(h2), f3 = __bfloat1622float2(h3);
            uint32_t l0 = bfpack(p.x - f0.x, p.y - f0.y);
            uint32_t l1 = bfpack(p.z - f1.x, p.w - f1.y);
            uint32_t l2 = bfpack(q.x - f2.x, q.y - f2.y);
            uint32_t l3 = bfpack(q.z - f3.x, q.w - f3.y);
            uint32_t la = rowaddr + (((8 + 4 * gh + t) ^ rx) << 4);
            sts4(la, l0, l1, l2, l3);
        }
    };

    // ---- prologue: fill buffer 0 for offset 0 ----
    {
        for (int e = tid; e < 1024; e += THREADS)
            cp16(sbase + SM_B(0) + e * 16, WB + 0 * 8192 + e * 8);
        asm volatile("cp.async.commit_group;" ::: "memory");
        float4 v[8];
        gatherA(0, v);
        stsA(sbase + SM_A(0), v);
        asm volatile("cp.async.wait_group 0;" ::: "memory");
    }
    __syncthreads();

    const int AOF[12] = {0,16,32,48, 0,16,32,48, 64,80,96,112};
    const int BOF[12] = {0,16,32,48, 64,80,96,112, 0,16,32,48};

    for (int k = 0; k < KOFF; k++) {
        const int buf = k & 1;
        float4 v[8];
        if (k + 1 < KOFF) {
            for (int e = tid; e < 1024; e += THREADS)
                cp16(sbase + SM_B(buf ^ 1) + e * 16, WB + (k + 1) * 8192 + e * 8);
            asm volatile("cp.async.commit_group;" ::: "memory");
            gatherA(k + 1, v);   // LDGs in flight during MMA below
        }

        const uint32_t abuf = sbase + SM_A(buf);
        const uint32_t bbuf = sbase + SM_B(buf);
        const uint32_t arow0 = abuf + (warp_m * 32 + arow) * 256;
        const uint32_t arow1 = arow0 + 16 * 256;
        const uint32_t brow0 = bbuf + (warp_n * 32 + brow) * 256;
        const uint32_t brow1 = brow0 + 16 * 256;

#pragma unroll
        for (int s = 0; s < 12; s++) {
            const int ach = (AOF[s] >> 3) + asel;
            const int bch = (BOF[s] >> 3) + bsel;
            uint32_t af[2][4], bf[2][4];
            ldsm4(af[0], arow0 + ((ach ^ r7) << 4));
            ldsm4(af[1], arow1 + ((ach ^ r7) << 4));
            ldsm4(bf[0], brow0 + ((bch ^ r7) << 4));
            ldsm4(bf[1], brow1 + ((bch ^ r7) << 4));
#pragma unroll
            for (int mt = 0; mt < 2; mt++)
#pragma unroll
                for (int nt = 0; nt < 4; nt++)
                    mma16816(acc[mt][nt], af[mt], &bf[nt >> 1][(nt & 1) * 2]);
        }

        if (k + 1 < KOFF) {
            stsA(sbase + SM_A(buf ^ 1), v);
            asm volatile("cp.async.wait_group 0;" ::: "memory");
        }
        __syncthreads();
    }

    // ---- epilogue: bias, store, stats ----
    const int gid = lane >> 2, tg = lane & 3;
    float s[8], q[8];
#pragma unroll
    for (int j = 0; j < 8; j++) { s[j] = 0.0f; q[j] = 0.0f; }

#pragma unroll
    for (int mt = 0; mt < 2; mt++) {
#pragma unroll
        for (int hf = 0; hf < 2; hf++) {
            const int grow = row0 + warp_m * 32 + mt * 16 + gid + hf * 8;
            const bool ok = grow < n;
            float* op = out + (size_t)grow * CDIM;
#pragma unroll
            for (int nt = 0; nt < 4; nt++) {
                const int col0 = warp_n * 32 + nt * 8 + 2 * tg;
                float x0 = acc[mt][nt][hf * 2 + 0] + sb[col0];
                float x1 = acc[mt][nt][hf * 2 + 1] + sb[col0 + 1];
                if (ok) {
                    *(float2*)(op + col0) = make_float2(x0, x1);
                    s[nt * 2 + 0] += x0;  q[nt * 2 + 0] += x0 * x0;
                    s[nt * 2 + 1] += x1;  q[nt * 2 + 1] += x1 * x1;
                }
            }
        }
    }
#pragma unroll
    for (int j = 0; j < 8; j++) {
#pragma unroll
        for (int off = 4; off < 32; off <<= 1) {
            s[j] += __shfl_xor_sync(0xFFFFFFFFu, s[j], off);
            q[j] += __shfl_xor_sync(0xFFFFFFFFu, q[j], off);
        }
    }
    if (lane < 4) {
#pragma unroll
        for (int j = 0; j < 8; j++) {
            const int col = warp_n * 32 + (j >> 1) * 8 + 2 * lane + (j & 1);
            atomicAdd(&sred[col], s[j]);
            atomicAdd(&sred[64 + col], q[j]);
        }
    }
    __syncthreads();
    if (tid < CDIM)           atomicAdd(&g_sum[tid], sred[tid]);
    else if (tid < 2 * CDIM)  atomicAdd(&g_sq[tid - CDIM], sred[tid]);
}

__global__ void stats_kernel(const float* __restrict__ gamma,
                             const float* __restrict__ beta, float inv_n)
{
    int c = threadIdx.x;
    if (c < CDIM) {
        float m   = g_sum[c] * inv_n;
        float var = g_sq[c] * inv_n - m * m;
        float rs  = rsqrtf(var + EPSV);
        float sc  = gamma[c] * rs;
        g_scale[c] = sc;
        g_shift[c] = beta[c] - sc * m;
    }
}

__global__ void apply_kernel(float* __restrict__ out, int total4)
{
    const float4* sc4 = (const float4*)g_scale;
    const float4* sh4 = (const float4*)g_shift;
    for (int i = blockIdx.x * blockDim.x + threadIdx.x; i < total4;
         i += gridDim.x * blockDim.x) {
        float4 v  = ((float4*)out)[i];
        float4 sc = sc4[i & 15];
        float4 sh = sh4[i & 15];
        float y0 = v.x * sc.x + sh.x;
        float y1 = v.y * sc.y + sh.y;
        float y2 = v.z * sc.z + sh.z;
        float y3 = v.w * sc.w + sh.w;
        const float L = 1.0f / 3.0f;
        v.x = y0 > 0.f ? y0 : y0 * L;
        v.y = y1 > 0.f ? y1 : y1 * L;
        v.z = y2 > 0.f ? y2 : y2 * L;
        v.w = y3 > 0.f ? y3 : y3 * L;
        ((float4*)out)[i] = v;
    }
}

extern "C" void kernel_launch(void* const* d_in, const int* in_sizes, int n_in,
                              void* d_out, int out_size)
{
    const float* feat  = (const float*)d_in[0];
    const float* W     = (const float*)d_in[1];
    const float* bias  = (const float*)d_in[2];
    const float* gamma = (const float*)d_in[3];
    const float* beta  = (const float*)d_in[4];
    const int*   nbr   = (const int*)d_in[5];
    const int n = in_sizes[0] / CDIM;

    cudaFuncSetAttribute(conv_kernel,
                         cudaFuncAttributeMaxDynamicSharedMemorySize, SMEM_BYTES);

    zero_stats_kernel<<<1, 128>>>();
    wprep_kernel<<<KOFF, 256>>>(W);
    conv_kernel<<<(n + MTILE - 1) / MTILE, THREADS, SMEM_BYTES>>>(
        feat, bias, nbr, (float*)d_out, n);
    stats_kernel<<<1, CDIM>>>(gamma, beta, 1.0f / (float)n);
    apply_kernel<<<2048, 256>>>((float*)d_out, n * (CDIM / 4));
}

// round 4
// speedup vs baseline: 3.5583x; 1.7757x over previous
#include <cuda_runtime.h>
#include <cuda_fp16.h>
#include <cstdint>

#define CDIM 64
#define KOFF 27
#define MTILE 128
#define THREADS 256
#define EPSV 1e-4f

// smem layout (bytes)
#define SM_RED   0                       // 128 floats
#define SM_BIAS  512                     // 64 floats
#define SM_A(b)  (1024 + (b)*16384)      // A: 128 rows x 128B fp16, swizzled
#define SM_B(b)  (33792 + (b)*8192)      // B: 64 rows x 128B fp16, swizzled
#define SMEM_BYTES 50176

__device__ float g_sum[CDIM];
__device__ float g_sq[CDIM];
__device__ float g_scale[CDIM];
__device__ float g_shift[CDIM];
__device__ __align__(16) __half WH[KOFF * 4096];  // B image: [k][n=64][kk=64] swizzled fp16

__device__ __forceinline__ uint32_t smem_u32(const void* p) {
    uint32_t a;
    asm("{ .reg .u64 t; cvta.to.shared.u64 t, %1; cvt.u32.u64 %0, t; }" : "=r"(a) : "l"(p));
    return a;
}
__device__ __forceinline__ void cp16(uint32_t dst, const void* src) {
    asm volatile("cp.async.cg.shared.global [%0], [%1], 16;"
                 :: "r"(dst), "l"(__cvta_generic_to_global(src)));
}
__device__ __forceinline__ void ldsm4(uint32_t* r, uint32_t addr) {
    asm volatile("ldmatrix.sync.aligned.m8n8.x4.shared.b16 {%0,%1,%2,%3}, [%4];"
                 : "=r"(r[0]), "=r"(r[1]), "=r"(r[2]), "=r"(r[3]) : "r"(addr));
}
__device__ __forceinline__ void mma16816(float* d, const uint32_t* a, const uint32_t* b) {
    asm volatile("mma.sync.aligned.m16n8k16.row.col.f32.f16.f16.f32 "
                 "{%0,%1,%2,%3}, {%4,%5,%6,%7}, {%8,%9}, {%0,%1,%2,%3};"
                 : "+f"(d[0]), "+f"(d[1]), "+f"(d[2]), "+f"(d[3])
                 : "r"(a[0]), "r"(a[1]), "r"(a[2]), "r"(a[3]), "r"(b[0]), "r"(b[1]));
}
__device__ __forceinline__ void sts4(uint32_t a, uint32_t x, uint32_t y, uint32_t z, uint32_t w) {
    asm volatile("st.shared.v4.u32 [%0], {%1,%2,%3,%4};" :: "r"(a), "r"(x), "r"(y), "r"(z), "r"(w) : "memory");
}
__device__ __forceinline__ uint32_t hpack(float a, float b) {
    __half2 t = __floats2half2_rn(a, b);
    return *reinterpret_cast<uint32_t*>(&t);
}

__global__ void zero_stats_kernel() {
    int t = threadIdx.x;
    if (t < CDIM) { g_sum[t] = 0.0f; g_sq[t] = 0.0f; }
}

// W[k][cin(kk)][cout(nn)] -> WH[k]: row nn (128B = 8 chunks of 8 fp16), chunk = (kk>>3)^(nn&7)
__global__ void wprep_kernel(const float* __restrict__ W) {
    int k = blockIdx.x;
    for (int e = threadIdx.x; e < 4096; e += 256) {
        int nn = e & 63, kk = e >> 6;
        float w = W[k * 4096 + kk * 64 + nn];
        WH[k * 4096 + nn * 64 + (((kk >> 3) ^ (nn & 7)) << 3) + (kk & 7)] = __float2half_rn(w);
    }
}

__global__ __launch_bounds__(THREADS, 3)
void conv_kernel(const float* __restrict__ feat,
                 const float* __restrict__ bias,
                 const int*   __restrict__ nbr,
                 float* __restrict__ out, int n)
{
    extern __shared__ char smem[];
    const uint32_t sbase = smem_u32(smem);
    float* sred = (float*)(smem + SM_RED);
    float* sb   = (float*)(smem + SM_BIAS);

    const int tid = threadIdx.x;
    const int wid = tid >> 5, lane = tid & 31;
    const int warp_m = wid & 3, warp_n = wid >> 2;
    const int row0 = blockIdx.x * MTILE;
    const float4* feat4 = (const float4*)feat;

    if (tid < 128) sred[tid] = 0.0f;
    if (tid < CDIM) sb[tid] = bias[tid];

    // gather mapping: 2 threads per row, each covers 32 floats (4 chunks)
    const int gr = tid >> 1, gh = tid & 1;
    const int rx = gr & 7;

    // ldmatrix lane components
    const int r7 = lane & 7;
    const int arow = ((lane >> 3) & 1) * 8 + r7;
    const int asel = lane >> 4;
    const int brow = ((lane >> 4) & 1) * 8 + r7;
    const int bsel = (lane >> 3) & 1;

    float acc[2][4][4];
#pragma unroll
    for (int mt = 0; mt < 2; mt++)
#pragma unroll
        for (int nt = 0; nt < 4; nt++)
#pragma unroll
            for (int j = 0; j < 4; j++) acc[mt][nt][j] = 0.0f;

    auto gatherA = [&](int k, float4 v[8]) {
        const int grow = row0 + gr;
        int idx = (grow < n) ? nbr[grow * KOFF + k] : n;
        const bool ok = idx < n;
        const float4* src = feat4 + (size_t)(ok ? idx : 0) * 16 + gh * 8;
#pragma unroll
        for (int j = 0; j < 8; j++)
            v[j] = ok ? src[j] : make_float4(0.f, 0.f, 0.f, 0.f);
    };
    auto stsA = [&](uint32_t abuf, const float4 v[8]) {
        const uint32_t rowaddr = abuf + gr * 128;
#pragma unroll
        for (int t = 0; t < 4; t++) {
            float4 p = v[2 * t], q = v[2 * t + 1];
            uint32_t h0 = hpack(p.x, p.y), h1 = hpack(p.z, p.w);
            uint32_t h2 = hpack(q.x, q.y), h3 = hpack(q.z, q.w);
            sts4(rowaddr + (((4 * gh + t) ^ rx) << 4), h0, h1, h2, h3);
        }
    };

    // prologue: fill buffer 0 for offset 0
    {
        for (int e = tid; e < 512; e += THREADS)
            cp16(sbase + SM_B(0) + e * 16, WH + e * 8);
        asm volatile("cp.async.commit_group;" ::: "memory");
        float4 v[8];
        gatherA(0, v);
        stsA(sbase + SM_A(0), v);
        asm volatile("cp.async.wait_group 0;" ::: "memory");
    }
    __syncthreads();

    for (int k = 0; k < KOFF; k++) {
        const int buf = k & 1;
        float4 v[8];
        if (k + 1 < KOFF) {
            for (int e = tid; e < 512; e += THREADS)
                cp16(sbase + SM_B(buf ^ 1) + e * 16, WH + (k + 1) * 4096 + e * 8);
            asm volatile("cp.async.commit_group;" ::: "memory");
            gatherA(k + 1, v);   // LDGs in flight during MMA below
        }

        const uint32_t arow0 = sbase + SM_A(buf) + (warp_m * 32 + arow) * 128;
        const uint32_t arow1 = arow0 + 16 * 128;
        const uint32_t brow0 = sbase + SM_B(buf) + (warp_n * 32 + brow) * 128;
        const uint32_t brow1 = brow0 + 16 * 128;

#pragma unroll
        for (int s = 0; s < 4; s++) {
            const int ach = 2 * s + asel;
            const int bch = 2 * s + bsel;
            uint32_t af[2][4], bf[2][4];
            ldsm4(af[0], arow0 + ((ach ^ r7) << 4));
            ldsm4(af[1], arow1 + ((ach ^ r7) << 4));
            ldsm4(bf[0], brow0 + ((bch ^ r7) << 4));
            ldsm4(bf[1], brow1 + ((bch ^ r7) << 4));
#pragma unroll
            for (int mt = 0; mt < 2; mt++)
#pragma unroll
                for (int nt = 0; nt < 4; nt++)
                    mma16816(acc[mt][nt], af[mt], &bf[nt >> 1][(nt & 1) * 2]);
        }

        if (k + 1 < KOFF) {
            stsA(sbase + SM_A(buf ^ 1), v);
            asm volatile("cp.async.wait_group 0;" ::: "memory");
        }
        __syncthreads();
    }

    // epilogue: bias, store, stats
    const int gid = lane >> 2, tg = lane & 3;
    float s[8], q[8];
#pragma unroll
    for (int j = 0; j < 8; j++) { s[j] = 0.0f; q[j] = 0.0f; }

#pragma unroll
    for (int mt = 0; mt < 2; mt++) {
#pragma unroll
        for (int hf = 0; hf < 2; hf++) {
            const int grow = row0 + warp_m * 32 + mt * 16 + gid + hf * 8;
            const bool ok = grow < n;
            float* op = out + (size_t)grow * CDIM;
#pragma unroll
            for (int nt = 0; nt < 4; nt++) {
                const int col0 = warp_n * 32 + nt * 8 + 2 * tg;
                float x0 = acc[mt][nt][hf * 2 + 0] + sb[col0];
                float x1 = acc[mt][nt][hf * 2 + 1] + sb[col0 + 1];
                if (ok) {
                    *(float2*)(op + col0) = make_float2(x0, x1);
                    s[nt * 2 + 0] += x0;  q[nt * 2 + 0] += x0 * x0;
                    s[nt * 2 + 1] += x1;  q[nt * 2 + 1] += x1 * x1;
                }
            }
        }
    }
#pragma unroll
    for (int j = 0; j < 8; j++) {
#pragma unroll
        for (int off = 4; off < 32; off <<= 1) {
            s[j] += __shfl_xor_sync(0xFFFFFFFFu, s[j], off);
            q[j] += __shfl_xor_sync(0xFFFFFFFFu, q[j], off);
        }
    }
    if (lane < 4) {
#pragma unroll
        for (int j = 0; j < 8; j++) {
            const int col = warp_n * 32 + (j >> 1) * 8 + 2 * lane + (j & 1);
            atomicAdd(&sred[col], s[j]);
            atomicAdd(&sred[64 + col], q[j]);
        }
    }
    __syncthreads();
    if (tid < CDIM)           atomicAdd(&g_sum[tid], sred[tid]);
    else if (tid < 2 * CDIM)  atomicAdd(&g_sq[tid - CDIM], sred[tid]);
}

__global__ void stats_kernel(const float* __restrict__ gamma,
                             const float* __restrict__ beta, float inv_n)
{
    int c = threadIdx.x;
    if (c < CDIM) {
        float m   = g_sum[c] * inv_n;
        float var = g_sq[c] * inv_n - m * m;
        float rs  = rsqrtf(var + EPSV);
        float sc  = gamma[c] * rs;
        g_scale[c] = sc;
        g_shift[c] = beta[c] - sc * m;
    }
}

__global__ void apply_kernel(float* __restrict__ out, int total4)
{
    const float4* sc4 = (const float4*)g_scale;
    const float4* sh4 = (const float4*)g_shift;
    for (int i = blockIdx.x * blockDim.x + threadIdx.x; i < total4;
         i += gridDim.x * blockDim.x) {
        float4 v  = ((float4*)out)[i];
        float4 sc = sc4[i & 15];
        float4 sh = sh4[i & 15];
        float y0 = v.x * sc.x + sh.x;
        float y1 = v.y * sc.y + sh.y;
        float y2 = v.z * sc.z + sh.z;
        float y3 = v.w * sc.w + sh.w;
        const float L = 1.0f / 3.0f;
        v.x = y0 > 0.f ? y0 : y0 * L;
        v.y = y1 > 0.f ? y1 : y1 * L;
        v.z = y2 > 0.f ? y2 : y2 * L;
        v.w = y3 > 0.f ? y3 : y3 * L;
        ((float4*)out)[i] = v;
    }
}

extern "C" void kernel_launch(void* const* d_in, const int* in_sizes, int n_in,
                              void* d_out, int out_size)
{
    const float* feat  = (const float*)d_in[0];
    const float* W     = (const float*)d_in[1];
    const float* bias  = (const float*)d_in[2];
    const float* gamma = (const float*)d_in[3];
    const float* beta  = (const float*)d_in[4];
    const int*   nbr   = (const int*)d_in[5];
    const int n = in_sizes[0] / CDIM;

    cudaFuncSetAttribute(conv_kernel,
                         cudaFuncAttributeMaxDynamicSharedMemorySize, SMEM_BYTES);

    zero_stats_kernel<<<1, 128>>>();
    wprep_kernel<<<KOFF, 256>>>(W);
    conv_kernel<<<(n + MTILE - 1) / MTILE, THREADS, SMEM_BYTES>>>(
        feat, bias, nbr, (float*)d_out, n);
    stats_kernel<<<1, CDIM>>>(gamma, beta, 1.0f / (float)n);
    apply_kernel<<<2048, 256>>>((float*)d_out, n * (CDIM / 4));
}